// round 15
// baseline (speedup 1.0000x reference)
#include <cuda_runtime.h>
#include <cuda_bf16.h>
#include <cuda_fp16.h>
#include <cstdint>

// ============================================================================
// TinyTransformerBlock on GB300 (compute_103 PTX -> HMMA fp16 tensor cores).
//  - QKV projection:  1-term fp16
//  - Attention:       fp16 HMMA, fp16 scores, shuffle softmax
//  - O projection:    1-term fp16
//  - MoE up/down:     fp16, gating fused via atomic RED.ADD
//  - 2 CTAs/SM forced on GEMM; W1/W2 prep + gates overlapped on side stream
// fp32 accumulation in all HMMA. Softmax/gates math fp32.
// ============================================================================

__device__ __forceinline__ uint32_t smem_to_u32(const void* p) {
    uint32_t a;
    asm("{ .reg .u64 t; cvta.to.shared.u64 t, %1; cvt.u32.u64 %0, t; }" : "=r"(a) : "l"(p));
    return a;
}
__device__ __forceinline__ void cp16(uint32_t saddr, const void* g) {
    asm volatile("cp.async.cg.shared.global [%0], [%1], 16;" :: "r"(saddr), "l"(g));
}
#define CP_COMMIT() asm volatile("cp.async.commit_group;" ::: "memory")
#define CP_WAIT_1() asm volatile("cp.async.wait_group 1;" ::: "memory")

__device__ __forceinline__ void ldm_x4(uint32_t* r, uint32_t addr) {
    asm volatile("ldmatrix.sync.aligned.m8n8.x4.shared.b16 {%0,%1,%2,%3}, [%4];"
        : "=r"(r[0]), "=r"(r[1]), "=r"(r[2]), "=r"(r[3]) : "r"(addr));
}
__device__ __forceinline__ void mma_16816(float* c, const uint32_t* a, uint32_t b0, uint32_t b1) {
    asm volatile("mma.sync.aligned.m16n8k16.row.col.f32.f16.f16.f32 "
        "{%0,%1,%2,%3}, {%4,%5,%6,%7}, {%8,%9}, {%0,%1,%2,%3};"
        : "+f"(c[0]), "+f"(c[1]), "+f"(c[2]), "+f"(c[3])
        : "r"(a[0]), "r"(a[1]), "r"(a[2]), "r"(a[3]), "r"(b0), "r"(b1));
}

// ---------------- problem sizes ----------------
#define MT 4096
#define HH 1024
#define DD 4096
#define EE 8
#define SQ 1024
#define BB 4

// ---------------- scratch (device globals; allocation-free) ----------------
__device__ __align__(1024) float g_x2[(long long)MT * HH];
__device__ __align__(1024) float g_g[(long long)MT * EE];
__device__ __align__(1024) __half g_x16[(long long)MT * HH];
__device__ __align__(1024) __half g_qkv16[3ULL * MT * HH];
__device__ __align__(1024) __half g_s16[(long long)BB * SQ * SQ];
__device__ __align__(1024) __half g_ps[(long long)MT * SQ];
__device__ __align__(1024) __half g_vts[(long long)BB * HH * SQ];
__device__ __align__(1024) __half g_a16[(long long)MT * HH];
__device__ __align__(1024) __half g_x2s[(long long)MT * HH];
__device__ __align__(1024) __half g_wqkvo[4ULL * HH * HH];
__device__ __align__(1024) __half g_w1ts[(long long)EE * DD * HH];
__device__ __align__(1024) __half g_w2ts[(long long)EE * HH * DD];
__device__ __align__(1024) __half g_hs[(long long)EE * MT * DD];

struct PtrArr { const float* p[8]; };

// ---------------- HMMA GEMM ----------------
enum { TE_BIAS_CVT16 = 0,
       TE_SCALE_CVT16 = 1,
       TE_CVT16 = 2,
       TE_BIAS_RESID_CVT1 = 3,
       TE_BIAS_RELU_CVT16 = 4,
       TE_GATED_RED = 5 };

#define HG_STAGE 32768
#define HG_SMEM (3 * HG_STAGE)

__device__ __forceinline__ void load_tile_cp(uint32_t sbase, const __half* g,
                                             long long ld, int row0, int k0, int tid)
{
    const int r = tid >> 1;
    const int c0 = (tid & 1) * 4;
    const __half* gp = g + (long long)(row0 + r) * ld + k0 + c0 * 8;
    const uint32_t srow = sbase + r * 128;
#pragma unroll
    for (int i = 0; i < 4; i++)
        cp16(srow + (((c0 + i) ^ (r & 7)) << 4), gp + i * 8);
}

template <int EPI>
__global__ void __launch_bounds__(256, 2)
hmma_gemm(const __half* __restrict__ A, long long aZ,
          const __half* __restrict__ B, long long bZ,
          int Kp, float* C, long long cZ, PtrArr bias, const float* resid,
          __half* cvt, long long cvtZ, int cvtK,
          const float* __restrict__ gate, float alpha)
{
    extern __shared__ __align__(1024) char smem[];
    const uint32_t sb = smem_to_u32(smem);
    const int tid = threadIdx.x;
    const int wid = tid >> 5, lane = tid & 31;
    const int z = blockIdx.z;
    const int m0 = blockIdx.y << 7;
    const int n0 = blockIdx.x << 7;
    const int Nt = gridDim.x << 7;
    const __half* Az = A + (long long)z * aZ;
    const __half* Bz = B + (long long)z * bZ;
    const int nch = Kp >> 6;

    const int wm = (wid >> 2) * 64;
    const int wn = (wid & 3) * 32;

    float acc[4][4][4];
#pragma unroll
    for (int i = 0; i < 4; i++)
#pragma unroll
        for (int j = 0; j < 4; j++)
#pragma unroll
            for (int r = 0; r < 4; r++) acc[i][j][r] = 0.0f;

    load_tile_cp(sb, Az, Kp, m0, 0, tid);
    load_tile_cp(sb + 16384, Bz, Kp, n0, 0, tid);
    CP_COMMIT();
    load_tile_cp(sb + HG_STAGE, Az, Kp, m0, 64, tid);
    load_tile_cp(sb + HG_STAGE + 16384, Bz, Kp, n0, 64, tid);
    CP_COMMIT();

    const int arow = lane & 15;
    const int ahalf = lane >> 4;
    const int brow = (lane & 7) + ((lane >> 4) & 1) * 8;
    const int bhalf = (lane >> 3) & 1;

    for (int c = 0; c < nch; c++) {
        CP_WAIT_1();
        __syncthreads();
        if (c + 2 < nch) {
            const uint32_t st = sb + ((c + 2) % 3) * HG_STAGE;
            load_tile_cp(st, Az, Kp, m0, (c + 2) * 64, tid);
            load_tile_cp(st + 16384, Bz, Kp, n0, (c + 2) * 64, tid);
        }
        CP_COMMIT();

        const uint32_t sA = sb + (c % 3) * HG_STAGE;
        const uint32_t sB = sA + 16384;
#pragma unroll
        for (int ks = 0; ks < 4; ks++) {
            uint32_t a[4][4];
#pragma unroll
            for (int mi = 0; mi < 4; mi++) {
                const int row = wm + mi * 16 + arow;
                const int ch = ks * 2 + ahalf;
                ldm_x4(a[mi], sA + row * 128 + ((ch ^ (row & 7)) << 4));
            }
            uint32_t b[2][4];
#pragma unroll
            for (int gI = 0; gI < 2; gI++) {
                const int row = wn + gI * 16 + brow;
                const int ch = ks * 2 + bhalf;
                ldm_x4(b[gI], sB + row * 128 + ((ch ^ (row & 7)) << 4));
            }
#pragma unroll
            for (int mi = 0; mi < 4; mi++)
#pragma unroll
                for (int ni = 0; ni < 4; ni++) {
                    const int gI = ni >> 1, off = (ni & 1) * 2;
                    mma_16816(acc[mi][ni], a[mi], b[gI][off], b[gI][off + 1]);
                }
        }
        __syncthreads();
    }

    // ---- epilogue ----
    const int l4 = lane >> 2, l2 = (lane & 3) << 1;
    float* Cz = C ? C + (long long)z * cZ : nullptr;
    const float* bz = bias.p[z];
    __half* cvz = cvt ? cvt + (long long)z * cvtZ : nullptr;

#pragma unroll
    for (int mi = 0; mi < 4; mi++)
#pragma unroll
        for (int h = 0; h < 2; h++) {
            const long long m = (long long)m0 + wm + mi * 16 + l4 + h * 8;
            float ge = 0.0f;
            if (EPI == TE_GATED_RED) ge = gate[m * EE + z];
#pragma unroll
            for (int ni = 0; ni < 4; ni++) {
                const long long n = n0 + wn + ni * 8 + l2;
                float v0 = acc[mi][ni][h * 2 + 0];
                float v1 = acc[mi][ni][h * 2 + 1];
                if (EPI == TE_BIAS_CVT16 || EPI == TE_BIAS_RESID_CVT1 ||
                    EPI == TE_BIAS_RELU_CVT16) {
                    v0 += bz[n]; v1 += bz[n + 1];
                }
                if (EPI == TE_SCALE_CVT16) { v0 *= alpha; v1 *= alpha; }
                if (EPI == TE_BIAS_RELU_CVT16) {
                    v0 = fmaxf(v0, 0.0f); v1 = fmaxf(v1, 0.0f);
                }
                if (EPI == TE_BIAS_RESID_CVT1) {
                    float2 rv = *(const float2*)&resid[m * Nt + n];
                    v0 += rv.x; v1 += rv.y;
                }
                if (EPI == TE_BIAS_RESID_CVT1) {
                    float2 o; o.x = v0; o.y = v1;
                    *(float2*)&Cz[m * Nt + n] = o;
                }
                if (EPI == TE_GATED_RED) {
                    atomicAdd(&Cz[m * Nt + n], ge * v0);
                    atomicAdd(&Cz[m * Nt + n + 1], ge * v1);
                }
                if (EPI != TE_GATED_RED) {
                    *(__half2*)&cvz[m * cvtK + n] =
                        __halves2half2(__float2half_rn(v0), __float2half_rn(v1));
                }
            }
        }
}

// ---------------- aux kernels ----------------
__global__ void cvt16(const float* __restrict__ in, __half* __restrict__ out)
{
    const long long i = (long long)blockIdx.x * blockDim.x + threadIdx.x;
    float4 v = ((const float4*)in)[i];
    __half2 a = __floats2half2_rn(v.x, v.y);
    __half2 b = __floats2half2_rn(v.z, v.w);
    uint2 u; u.x = *(uint32_t*)&a; u.y = *(uint32_t*)&b;
    ((uint2*)out)[i] = u;
}

__global__ void transpose_cvt(PtrArr in, int K, int N,
                              __half* __restrict__ out, long long outZ)
{
    __shared__ float t[64][65];
    const float* src = in.p[blockIdx.z];
    __half* dst = out + blockIdx.z * outZ;
    const int n0 = blockIdx.x * 64, k0 = blockIdx.y * 64;
    const int lr = threadIdx.x >> 4;
    const int lc = (threadIdx.x & 15) * 4;
#pragma unroll
    for (int j = 0; j < 4; j++) {
        const int r = lr + j * 16;
        float4 v = *(const float4*)&src[(long long)(k0 + r) * N + n0 + lc];
        t[r][lc] = v.x; t[r][lc + 1] = v.y; t[r][lc + 2] = v.z; t[r][lc + 3] = v.w;
    }
    __syncthreads();
    const int orow = threadIdx.x >> 2;
    const int oc = threadIdx.x & 3;
    __half* obase = dst + (long long)(n0 + orow) * K + k0;
#pragma unroll
    for (int j = 0; j < 4; j++) {
        const int kq = (oc + j * 4) * 4;
        __half2 a = __floats2half2_rn(t[kq][orow], t[kq + 1][orow]);
        __half2 b = __floats2half2_rn(t[kq + 2][orow], t[kq + 3][orow]);
        uint2 u; u.x = *(uint32_t*)&a; u.y = *(uint32_t*)&b;
        *(uint2*)&obase[kq] = u;
    }
}

__global__ void transpose_h(const __half* __restrict__ in, long long inZ,
                            __half* __restrict__ out, long long outZ, int K, int N)
{
    __shared__ __half t[64][66];
    const __half* src = in + blockIdx.z * inZ;
    __half* dst = out + blockIdx.z * outZ;
    const int n0 = blockIdx.x * 64, k0 = blockIdx.y * 64;
    const int lr = threadIdx.x >> 4;
    const int lc = (threadIdx.x & 15) * 4;
#pragma unroll
    for (int j = 0; j < 4; j++) {
        const int r = lr + j * 16;
        uint2 v = *(const uint2*)&src[(long long)(k0 + r) * N + n0 + lc];
        *(__half2*)&t[r][lc] = *(__half2*)&v.x;
        *(__half2*)&t[r][lc + 2] = *(__half2*)&v.y;
    }
    __syncthreads();
    const int orow = threadIdx.x >> 2;
    const int oc = threadIdx.x & 3;
    __half* obase = dst + (long long)(n0 + orow) * K + k0;
#pragma unroll
    for (int j = 0; j < 4; j++) {
        const int kq = (oc + j * 4) * 4;
        __half2 a = __halves2half2(t[kq][orow], t[kq + 1][orow]);
        __half2 b = __halves2half2(t[kq + 2][orow], t[kq + 3][orow]);
        uint2 u; u.x = *(uint32_t*)&a; u.y = *(uint32_t*)&b;
        *(uint2*)&obase[kq] = u;
    }
}

__global__ void softmax_rows(const __half* __restrict__ S, __half* __restrict__ P)
{
    const int row = blockIdx.x, tid = threadIdx.x;
    const int lane = tid & 31, wid = tid >> 5;
    uint2 u = ((const uint2*)(S + (long long)row * SQ))[tid];
    __half2 h01 = *(__half2*)&u.x, h23 = *(__half2*)&u.y;
    float v0 = __low2float(h01), v1 = __high2float(h01);
    float v2 = __low2float(h23), v3 = __high2float(h23);
    float m = fmaxf(fmaxf(v0, v1), fmaxf(v2, v3));
#pragma unroll
    for (int o = 16; o; o >>= 1) m = fmaxf(m, __shfl_xor_sync(0xFFFFFFFFu, m, o));
    __shared__ float wm[8], ws[8];
    if (lane == 0) wm[wid] = m;
    __syncthreads();
    m = wm[0];
#pragma unroll
    for (int w = 1; w < 8; w++) m = fmaxf(m, wm[w]);
    float e0 = __expf(v0 - m), e1 = __expf(v1 - m);
    float e2 = __expf(v2 - m), e3 = __expf(v3 - m);
    float sum = e0 + e1 + e2 + e3;
#pragma unroll
    for (int o = 16; o; o >>= 1) sum += __shfl_xor_sync(0xFFFFFFFFu, sum, o);
    if (lane == 0) ws[wid] = sum;
    __syncthreads();
    sum = 0.0f;
#pragma unroll
    for (int w = 0; w < 8; w++) sum += ws[w];
    const float inv = 1.0f / sum;
    __half2 a = __floats2half2_rn(e0 * inv, e1 * inv);
    __half2 b = __floats2half2_rn(e2 * inv, e3 * inv);
    uint2 o2; o2.x = *(uint32_t*)&a; o2.y = *(uint32_t*)&b;
    ((uint2*)(P + (long long)row * SQ))[tid] = o2;
}

__global__ void gates_out(const float* __restrict__ x2, const float* __restrict__ Wg,
                          const float* __restrict__ bg, const float* __restrict__ b2,
                          float* __restrict__ G, float* __restrict__ out)
{
    const int row = blockIdx.x, tid = threadIdx.x;
    const int lane = tid & 31, wid = tid >> 5;
    float4 xv = ((const float4*)(x2 + (long long)row * HH))[tid];
    float xa[4] = {xv.x, xv.y, xv.z, xv.w};
    float part[8];
#pragma unroll
    for (int e = 0; e < 8; e++) part[e] = 0.0f;
    const float* w = Wg + (long long)tid * 4 * 8;
#pragma unroll
    for (int i = 0; i < 4; i++)
#pragma unroll
        for (int e = 0; e < 8; e++)
            part[e] = fmaf(xa[i], w[i * 8 + e], part[e]);
#pragma unroll
    for (int e = 0; e < 8; e++)
#pragma unroll
        for (int o = 16; o; o >>= 1)
            part[e] += __shfl_xor_sync(0xFFFFFFFFu, part[e], o);
    __shared__ float wsum[8][9];
    if (lane == 0) {
#pragma unroll
        for (int e = 0; e < 8; e++) wsum[wid][e] = part[e];
    }
    __syncthreads();
    __shared__ float gsh[8];
    if (tid < 8) {
        float v = 0.0f;
#pragma unroll
        for (int w8 = 0; w8 < 8; w8++) v += wsum[w8][tid];
        gsh[tid] = v + bg[tid];
    }
    __syncthreads();
    if (tid == 0) {
        float m = -1e30f;
#pragma unroll
        for (int e = 0; e < 8; e++) m = fmaxf(m, gsh[e]);
        float ex[8], s = 0.0f;
#pragma unroll
        for (int e = 0; e < 8; e++) { ex[e] = __expf(gsh[e] - m); s += ex[e]; }
        const float inv = 1.0f / s;
#pragma unroll
        for (int e = 0; e < 8; e++) gsh[e] = ex[e] * inv;
    }
    __syncthreads();
    if (tid < 8) G[row * 8 + tid] = gsh[tid];
    float4 acc = xv;
#pragma unroll
    for (int e = 0; e < 8; e++) {
        const float ge = gsh[e];
        float4 b = ((const float4*)(b2 + e * HH))[tid];
        acc.x = fmaf(ge, b.x, acc.x); acc.y = fmaf(ge, b.y, acc.y);
        acc.z = fmaf(ge, b.z, acc.z); acc.w = fmaf(ge, b.w, acc.w);
    }
    ((float4*)(out + (long long)row * HH))[tid] = acc;
}

// ---------------- host side ----------------
extern "C" void kernel_launch(void* const* d_in, const int* in_sizes, int n_in,
                              void* d_out, int out_size)
{
    const float* x  = (const float*)d_in[0];
    const float* Wq = (const float*)d_in[1];
    const float* bq = (const float*)d_in[2];
    const float* Wk = (const float*)d_in[3];
    const float* bk = (const float*)d_in[4];
    const float* Wv = (const float*)d_in[5];
    const float* bv = (const float*)d_in[6];
    const float* Wo = (const float*)d_in[7];
    const float* bo = (const float*)d_in[8];
    const float* Wg = (const float*)d_in[9];
    const float* bg = (const float*)d_in[10];
    const float* W1 = (const float*)d_in[11];
    const float* b1 = (const float*)d_in[12];
    const float* W2 = (const float*)d_in[13];
    const float* b2 = (const float*)d_in[14];
    float* out = (float*)d_out;

    float *x2, *g;
    __half *x16, *qkv16, *s16, *ps, *vts, *a16, *x2s, *wqkvo, *w1ts, *w2ts, *hs;
    cudaGetSymbolAddress((void**)&x2, g_x2);
    cudaGetSymbolAddress((void**)&g, g_g);
    cudaGetSymbolAddress((void**)&x16, g_x16);
    cudaGetSymbolAddress((void**)&qkv16, g_qkv16);
    cudaGetSymbolAddress((void**)&s16, g_s16);
    cudaGetSymbolAddress((void**)&ps, g_ps);
    cudaGetSymbolAddress((void**)&vts, g_vts);
    cudaGetSymbolAddress((void**)&a16, g_a16);
    cudaGetSymbolAddress((void**)&x2s, g_x2s);
    cudaGetSymbolAddress((void**)&wqkvo, g_wqkvo);
    cudaGetSymbolAddress((void**)&w1ts, g_w1ts);
    cudaGetSymbolAddress((void**)&w2ts, g_w2ts);
    cudaGetSymbolAddress((void**)&hs, g_hs);

    cudaFuncSetAttribute(hmma_gemm<TE_BIAS_CVT16>, cudaFuncAttributeMaxDynamicSharedMemorySize, HG_SMEM);
    cudaFuncSetAttribute(hmma_gemm<TE_SCALE_CVT16>, cudaFuncAttributeMaxDynamicSharedMemorySize, HG_SMEM);
    cudaFuncSetAttribute(hmma_gemm<TE_CVT16>, cudaFuncAttributeMaxDynamicSharedMemorySize, HG_SMEM);
    cudaFuncSetAttribute(hmma_gemm<TE_BIAS_RESID_CVT1>, cudaFuncAttributeMaxDynamicSharedMemorySize, HG_SMEM);
    cudaFuncSetAttribute(hmma_gemm<TE_BIAS_RELU_CVT16>, cudaFuncAttributeMaxDynamicSharedMemorySize, HG_SMEM);
    cudaFuncSetAttribute(hmma_gemm<TE_GATED_RED>, cudaFuncAttributeMaxDynamicSharedMemorySize, HG_SMEM);

    PtrArr bnone = {};
    dim3 blk(256);

    // side stream for overlap (created per call; not destroyed -- destroying a
    // captured stream/event before EndCapture invalidates the capture; no
    // device-memory allocation is involved)
    cudaStream_t s1;
    cudaStreamCreate(&s1);
    cudaEvent_t evRoot, evPrep, evO, evGates;
    cudaEventCreateWithFlags(&evRoot, cudaEventDisableTiming);
    cudaEventCreateWithFlags(&evPrep, cudaEventDisableTiming);
    cudaEventCreateWithFlags(&evO, cudaEventDisableTiming);
    cudaEventCreateWithFlags(&evGates, cudaEventDisableTiming);

    cudaEventRecord(evRoot, 0);
    cudaStreamWaitEvent(s1, evRoot, 0);

    // ---- side stream: MoE weight transposes (needed only at step 6/7) ----
    {
        PtrArr wi;
        for (int e = 0; e < 8; e++) wi.p[e] = W1 + (long long)e * HH * DD;
        transpose_cvt<<<dim3(DD / 64, HH / 64, EE), blk, 0, s1>>>(wi, HH, DD, w1ts, (long long)HH * DD);
    }
    {
        PtrArr wi;
        for (int e = 0; e < 8; e++) wi.p[e] = W2 + (long long)e * DD * HH;
        transpose_cvt<<<dim3(HH / 64, DD / 64, EE), blk, 0, s1>>>(wi, DD, HH, w2ts, (long long)DD * HH);
    }
    cudaEventRecord(evPrep, s1);

    // ---- main stream: attention chain ----
    cvt16<<<(MT * HH / 4) / 256, blk>>>(x, x16);
    {
        PtrArr wi; wi.p[0] = Wq; wi.p[1] = Wk; wi.p[2] = Wv; wi.p[3] = Wo;
        transpose_cvt<<<dim3(HH / 64, HH / 64, 4), blk>>>(wi, HH, HH, wqkvo, (long long)HH * HH);
    }
    {
        PtrArr ba; ba.p[0] = bq; ba.p[1] = bk; ba.p[2] = bv;
        hmma_gemm<TE_BIAS_CVT16><<<dim3(HH / 128, MT / 128, 3), blk, HG_SMEM>>>(
            x16, 0, wqkvo, (long long)HH * HH, HH, nullptr, 0, ba,
            nullptr, qkv16, (long long)MT * HH, HH, nullptr, 0.0f);
    }
    const __half* q16 = qkv16;
    const __half* k16 = qkv16 + (long long)MT * HH;
    const __half* v16 = qkv16 + 2LL * MT * HH;

    hmma_gemm<TE_SCALE_CVT16><<<dim3(SQ / 128, SQ / 128, BB), blk, HG_SMEM>>>(
        q16, (long long)SQ * HH, k16, (long long)SQ * HH, HH,
        nullptr, 0, bnone, nullptr, s16, (long long)SQ * SQ, SQ, nullptr, 0.03125f);
    softmax_rows<<<BB * SQ, 256>>>(s16, ps);
    transpose_h<<<dim3(HH / 64, SQ / 64, BB), blk>>>(
        v16, (long long)SQ * HH, vts, (long long)HH * SQ, SQ, HH);
    hmma_gemm<TE_CVT16><<<dim3(HH / 128, SQ / 128, BB), blk, HG_SMEM>>>(
        ps, (long long)SQ * SQ, vts, (long long)HH * SQ, SQ,
        nullptr, 0, bnone, nullptr, a16, (long long)SQ * HH, HH, nullptr, 0.0f);

    {
        PtrArr ba; ba.p[0] = bo;
        hmma_gemm<TE_BIAS_RESID_CVT1><<<dim3(HH / 128, MT / 128, 1), blk, HG_SMEM>>>(
            a16, 0, wqkvo + 3ULL * HH * HH, 0, HH, x2, 0, ba, x, x2s, 0, HH,
            nullptr, 0.0f);
    }
    cudaEventRecord(evO, 0);

    // ---- side stream: gates + output base (overlaps up-proj) ----
    cudaStreamWaitEvent(s1, evO, 0);
    gates_out<<<MT, 256, 0, s1>>>(x2, Wg, bg, b2, g, out);
    cudaEventRecord(evGates, s1);

    // ---- main stream: MoE ----
    cudaStreamWaitEvent(0, evPrep, 0);
    {
        PtrArr ba;
        for (int e = 0; e < 8; e++) ba.p[e] = b1 + (long long)e * DD;
        hmma_gemm<TE_BIAS_RELU_CVT16><<<dim3(DD / 128, MT / 128, EE), blk, HG_SMEM>>>(
            x2s, 0, w1ts, (long long)HH * DD, HH, nullptr, 0, ba, nullptr,
            hs, (long long)MT * DD, DD, nullptr, 0.0f);
    }
    cudaStreamWaitEvent(0, evGates, 0);
    hmma_gemm<TE_GATED_RED><<<dim3(HH / 128, MT / 128, EE), blk, HG_SMEM>>>(
        hs, (long long)MT * DD, w2ts, (long long)DD * HH, DD, out, 0, bnone,
        nullptr, nullptr, 0, 0, g, 0.0f);
}

// round 17
// speedup vs baseline: 1.0039x; 1.0039x over previous
#include <cuda_runtime.h>
#include <cuda_bf16.h>
#include <cuda_fp16.h>
#include <cstdint>

// ============================================================================
// TinyTransformerBlock on GB300 (compute_103 PTX -> HMMA fp16 tensor cores).
//  - QKV projection:  1-term fp16
//  - Attention:       fp16 HMMA, fp16 scores, shuffle softmax
//  - O projection:    1-term fp16
//  - MoE up/down:     fp16, gating fused via atomic RED.ADD
//  - ONE side stream (driver-pool; extra streams allocate device mem -> banned):
//    W1/W2 transposes overlap attention chain; gates_out overlaps up-proj.
// fp32 accumulation in all HMMA. Softmax/gates math fp32.
// ============================================================================

__device__ __forceinline__ uint32_t smem_to_u32(const void* p) {
    uint32_t a;
    asm("{ .reg .u64 t; cvta.to.shared.u64 t, %1; cvt.u32.u64 %0, t; }" : "=r"(a) : "l"(p));
    return a;
}
__device__ __forceinline__ void cp16(uint32_t saddr, const void* g) {
    asm volatile("cp.async.cg.shared.global [%0], [%1], 16;" :: "r"(saddr), "l"(g));
}
#define CP_COMMIT() asm volatile("cp.async.commit_group;" ::: "memory")
#define CP_WAIT_1() asm volatile("cp.async.wait_group 1;" ::: "memory")

__device__ __forceinline__ void ldm_x4(uint32_t* r, uint32_t addr) {
    asm volatile("ldmatrix.sync.aligned.m8n8.x4.shared.b16 {%0,%1,%2,%3}, [%4];"
        : "=r"(r[0]), "=r"(r[1]), "=r"(r[2]), "=r"(r[3]) : "r"(addr));
}
__device__ __forceinline__ void mma_16816(float* c, const uint32_t* a, uint32_t b0, uint32_t b1) {
    asm volatile("mma.sync.aligned.m16n8k16.row.col.f32.f16.f16.f32 "
        "{%0,%1,%2,%3}, {%4,%5,%6,%7}, {%8,%9}, {%0,%1,%2,%3};"
        : "+f"(c[0]), "+f"(c[1]), "+f"(c[2]), "+f"(c[3])
        : "r"(a[0]), "r"(a[1]), "r"(a[2]), "r"(a[3]), "r"(b0), "r"(b1));
}

// ---------------- problem sizes ----------------
#define MT 4096
#define HH 1024
#define DD 4096
#define EE 8
#define SQ 1024
#define BB 4

// ---------------- scratch (device globals; allocation-free) ----------------
__device__ __align__(1024) float g_x2[(long long)MT * HH];
__device__ __align__(1024) float g_g[(long long)MT * EE];
__device__ __align__(1024) __half g_x16[(long long)MT * HH];
__device__ __align__(1024) __half g_qkv16[3ULL * MT * HH];
__device__ __align__(1024) __half g_s16[(long long)BB * SQ * SQ];
__device__ __align__(1024) __half g_ps[(long long)MT * SQ];
__device__ __align__(1024) __half g_vts[(long long)BB * HH * SQ];
__device__ __align__(1024) __half g_a16[(long long)MT * HH];
__device__ __align__(1024) __half g_x2s[(long long)MT * HH];
__device__ __align__(1024) __half g_wqkvo[4ULL * HH * HH];
__device__ __align__(1024) __half g_w1ts[(long long)EE * DD * HH];
__device__ __align__(1024) __half g_w2ts[(long long)EE * HH * DD];
__device__ __align__(1024) __half g_hs[(long long)EE * MT * DD];

struct PtrArr { const float* p[8]; };

// ---------------- HMMA GEMM ----------------
enum { TE_BIAS_CVT16 = 0,
       TE_SCALE_CVT16 = 1,
       TE_CVT16 = 2,
       TE_BIAS_RESID_CVT1 = 3,
       TE_BIAS_RELU_CVT16 = 4,
       TE_GATED_RED = 5 };

#define HG_STAGE 32768
#define HG_SMEM (3 * HG_STAGE)

__device__ __forceinline__ void load_tile_cp(uint32_t sbase, const __half* g,
                                             long long ld, int row0, int k0, int tid)
{
    const int r = tid >> 1;
    const int c0 = (tid & 1) * 4;
    const __half* gp = g + (long long)(row0 + r) * ld + k0 + c0 * 8;
    const uint32_t srow = sbase + r * 128;
#pragma unroll
    for (int i = 0; i < 4; i++)
        cp16(srow + (((c0 + i) ^ (r & 7)) << 4), gp + i * 8);
}

template <int EPI>
__global__ void __launch_bounds__(256)
hmma_gemm(const __half* __restrict__ A, long long aZ,
          const __half* __restrict__ B, long long bZ,
          int Kp, float* C, long long cZ, PtrArr bias, const float* resid,
          __half* cvt, long long cvtZ, int cvtK,
          const float* __restrict__ gate, float alpha)
{
    extern __shared__ __align__(1024) char smem[];
    const uint32_t sb = smem_to_u32(smem);
    const int tid = threadIdx.x;
    const int wid = tid >> 5, lane = tid & 31;
    const int z = blockIdx.z;
    const int m0 = blockIdx.y << 7;
    const int n0 = blockIdx.x << 7;
    const int Nt = gridDim.x << 7;
    const __half* Az = A + (long long)z * aZ;
    const __half* Bz = B + (long long)z * bZ;
    const int nch = Kp >> 6;

    const int wm = (wid >> 2) * 64;
    const int wn = (wid & 3) * 32;

    float acc[4][4][4];
#pragma unroll
    for (int i = 0; i < 4; i++)
#pragma unroll
        for (int j = 0; j < 4; j++)
#pragma unroll
            for (int r = 0; r < 4; r++) acc[i][j][r] = 0.0f;

    load_tile_cp(sb, Az, Kp, m0, 0, tid);
    load_tile_cp(sb + 16384, Bz, Kp, n0, 0, tid);
    CP_COMMIT();
    load_tile_cp(sb + HG_STAGE, Az, Kp, m0, 64, tid);
    load_tile_cp(sb + HG_STAGE + 16384, Bz, Kp, n0, 64, tid);
    CP_COMMIT();

    const int arow = lane & 15;
    const int ahalf = lane >> 4;
    const int brow = (lane & 7) + ((lane >> 4) & 1) * 8;
    const int bhalf = (lane >> 3) & 1;

    for (int c = 0; c < nch; c++) {
        CP_WAIT_1();
        __syncthreads();
        if (c + 2 < nch) {
            const uint32_t st = sb + ((c + 2) % 3) * HG_STAGE;
            load_tile_cp(st, Az, Kp, m0, (c + 2) * 64, tid);
            load_tile_cp(st + 16384, Bz, Kp, n0, (c + 2) * 64, tid);
        }
        CP_COMMIT();

        const uint32_t sA = sb + (c % 3) * HG_STAGE;
        const uint32_t sB = sA + 16384;
#pragma unroll
        for (int ks = 0; ks < 4; ks++) {
            uint32_t a[4][4];
#pragma unroll
            for (int mi = 0; mi < 4; mi++) {
                const int row = wm + mi * 16 + arow;
                const int ch = ks * 2 + ahalf;
                ldm_x4(a[mi], sA + row * 128 + ((ch ^ (row & 7)) << 4));
            }
            uint32_t b[2][4];
#pragma unroll
            for (int gI = 0; gI < 2; gI++) {
                const int row = wn + gI * 16 + brow;
                const int ch = ks * 2 + bhalf;
                ldm_x4(b[gI], sB + row * 128 + ((ch ^ (row & 7)) << 4));
            }
#pragma unroll
            for (int mi = 0; mi < 4; mi++)
#pragma unroll
                for (int ni = 0; ni < 4; ni++) {
                    const int gI = ni >> 1, off = (ni & 1) * 2;
                    mma_16816(acc[mi][ni], a[mi], b[gI][off], b[gI][off + 1]);
                }
        }
        __syncthreads();
    }

    // ---- epilogue ----
    const int l4 = lane >> 2, l2 = (lane & 3) << 1;
    float* Cz = C ? C + (long long)z * cZ : nullptr;
    const float* bz = bias.p[z];
    __half* cvz = cvt ? cvt + (long long)z * cvtZ : nullptr;

#pragma unroll
    for (int mi = 0; mi < 4; mi++)
#pragma unroll
        for (int h = 0; h < 2; h++) {
            const long long m = (long long)m0 + wm + mi * 16 + l4 + h * 8;
            float ge = 0.0f;
            if (EPI == TE_GATED_RED) ge = gate[m * EE + z];
#pragma unroll
            for (int ni = 0; ni < 4; ni++) {
                const long long n = n0 + wn + ni * 8 + l2;
                float v0 = acc[mi][ni][h * 2 + 0];
                float v1 = acc[mi][ni][h * 2 + 1];
                if (EPI == TE_BIAS_CVT16 || EPI == TE_BIAS_RESID_CVT1 ||
                    EPI == TE_BIAS_RELU_CVT16) {
                    v0 += bz[n]; v1 += bz[n + 1];
                }
                if (EPI == TE_SCALE_CVT16) { v0 *= alpha; v1 *= alpha; }
                if (EPI == TE_BIAS_RELU_CVT16) {
                    v0 = fmaxf(v0, 0.0f); v1 = fmaxf(v1, 0.0f);
                }
                if (EPI == TE_BIAS_RESID_CVT1) {
                    float2 rv = *(const float2*)&resid[m * Nt + n];
                    v0 += rv.x; v1 += rv.y;
                }
                if (EPI == TE_BIAS_RESID_CVT1) {
                    float2 o; o.x = v0; o.y = v1;
                    *(float2*)&Cz[m * Nt + n] = o;
                }
                if (EPI == TE_GATED_RED) {
                    atomicAdd(&Cz[m * Nt + n], ge * v0);
                    atomicAdd(&Cz[m * Nt + n + 1], ge * v1);
                }
                if (EPI != TE_GATED_RED) {
                    *(__half2*)&cvz[m * cvtK + n] =
                        __halves2half2(__float2half_rn(v0), __float2half_rn(v1));
                }
            }
        }
}

// ---------------- aux kernels ----------------
__global__ void cvt16(const float* __restrict__ in, __half* __restrict__ out)
{
    const long long i = (long long)blockIdx.x * blockDim.x + threadIdx.x;
    float4 v = ((const float4*)in)[i];
    __half2 a = __floats2half2_rn(v.x, v.y);
    __half2 b = __floats2half2_rn(v.z, v.w);
    uint2 u; u.x = *(uint32_t*)&a; u.y = *(uint32_t*)&b;
    ((uint2*)out)[i] = u;
}

__global__ void transpose_cvt(PtrArr in, int K, int N,
                              __half* __restrict__ out, long long outZ)
{
    __shared__ float t[64][65];
    const float* src = in.p[blockIdx.z];
    __half* dst = out + blockIdx.z * outZ;
    const int n0 = blockIdx.x * 64, k0 = blockIdx.y * 64;
    const int lr = threadIdx.x >> 4;
    const int lc = (threadIdx.x & 15) * 4;
#pragma unroll
    for (int j = 0; j < 4; j++) {
        const int r = lr + j * 16;
        float4 v = *(const float4*)&src[(long long)(k0 + r) * N + n0 + lc];
        t[r][lc] = v.x; t[r][lc + 1] = v.y; t[r][lc + 2] = v.z; t[r][lc + 3] = v.w;
    }
    __syncthreads();
    const int orow = threadIdx.x >> 2;
    const int oc = threadIdx.x & 3;
    __half* obase = dst + (long long)(n0 + orow) * K + k0;
#pragma unroll
    for (int j = 0; j < 4; j++) {
        const int kq = (oc + j * 4) * 4;
        __half2 a = __floats2half2_rn(t[kq][orow], t[kq + 1][orow]);
        __half2 b = __floats2half2_rn(t[kq + 2][orow], t[kq + 3][orow]);
        uint2 u; u.x = *(uint32_t*)&a; u.y = *(uint32_t*)&b;
        *(uint2*)&obase[kq] = u;
    }
}

__global__ void transpose_h(const __half* __restrict__ in, long long inZ,
                            __half* __restrict__ out, long long outZ, int K, int N)
{
    __shared__ __half t[64][66];
    const __half* src = in + blockIdx.z * inZ;
    __half* dst = out + blockIdx.z * outZ;
    const int n0 = blockIdx.x * 64, k0 = blockIdx.y * 64;
    const int lr = threadIdx.x >> 4;
    const int lc = (threadIdx.x & 15) * 4;
#pragma unroll
    for (int j = 0; j < 4; j++) {
        const int r = lr + j * 16;
        uint2 v = *(const uint2*)&src[(long long)(k0 + r) * N + n0 + lc];
        *(__half2*)&t[r][lc] = *(__half2*)&v.x;
        *(__half2*)&t[r][lc + 2] = *(__half2*)&v.y;
    }
    __syncthreads();
    const int orow = threadIdx.x >> 2;
    const int oc = threadIdx.x & 3;
    __half* obase = dst + (long long)(n0 + orow) * K + k0;
#pragma unroll
    for (int j = 0; j < 4; j++) {
        const int kq = (oc + j * 4) * 4;
        __half2 a = __halves2half2(t[kq][orow], t[kq + 1][orow]);
        __half2 b = __halves2half2(t[kq + 2][orow], t[kq + 3][orow]);
        uint2 u; u.x = *(uint32_t*)&a; u.y = *(uint32_t*)&b;
        *(uint2*)&obase[kq] = u;
    }
}

__global__ void softmax_rows(const __half* __restrict__ S, __half* __restrict__ P)
{
    const int row = blockIdx.x, tid = threadIdx.x;
    const int lane = tid & 31, wid = tid >> 5;
    uint2 u = ((const uint2*)(S + (long long)row * SQ))[tid];
    __half2 h01 = *(__half2*)&u.x, h23 = *(__half2*)&u.y;
    float v0 = __low2float(h01), v1 = __high2float(h01);
    float v2 = __low2float(h23), v3 = __high2float(h23);
    float m = fmaxf(fmaxf(v0, v1), fmaxf(v2, v3));
#pragma unroll
    for (int o = 16; o; o >>= 1) m = fmaxf(m, __shfl_xor_sync(0xFFFFFFFFu, m, o));
    __shared__ float wm[8], ws[8];
    if (lane == 0) wm[wid] = m;
    __syncthreads();
    m = wm[0];
#pragma unroll
    for (int w = 1; w < 8; w++) m = fmaxf(m, wm[w]);
    float e0 = __expf(v0 - m), e1 = __expf(v1 - m);
    float e2 = __expf(v2 - m), e3 = __expf(v3 - m);
    float sum = e0 + e1 + e2 + e3;
#pragma unroll
    for (int o = 16; o; o >>= 1) sum += __shfl_xor_sync(0xFFFFFFFFu, sum, o);
    if (lane == 0) ws[wid] = sum;
    __syncthreads();
    sum = 0.0f;
#pragma unroll
    for (int w = 0; w < 8; w++) sum += ws[w];
    const float inv = 1.0f / sum;
    __half2 a = __floats2half2_rn(e0 * inv, e1 * inv);
    __half2 b = __floats2half2_rn(e2 * inv, e3 * inv);
    uint2 o2; o2.x = *(uint32_t*)&a; o2.y = *(uint32_t*)&b;
    ((uint2*)(P + (long long)row * SQ))[tid] = o2;
}

__global__ void gates_out(const float* __restrict__ x2, const float* __restrict__ Wg,
                          const float* __restrict__ bg, const float* __restrict__ b2,
                          float* __restrict__ G, float* __restrict__ out)
{
    const int row = blockIdx.x, tid = threadIdx.x;
    const int lane = tid & 31, wid = tid >> 5;
    float4 xv = ((const float4*)(x2 + (long long)row * HH))[tid];
    float xa[4] = {xv.x, xv.y, xv.z, xv.w};
    float part[8];
#pragma unroll
    for (int e = 0; e < 8; e++) part[e] = 0.0f;
    const float* w = Wg + (long long)tid * 4 * 8;
#pragma unroll
    for (int i = 0; i < 4; i++)
#pragma unroll
        for (int e = 0; e < 8; e++)
            part[e] = fmaf(xa[i], w[i * 8 + e], part[e]);
#pragma unroll
    for (int e = 0; e < 8; e++)
#pragma unroll
        for (int o = 16; o; o >>= 1)
            part[e] += __shfl_xor_sync(0xFFFFFFFFu, part[e], o);
    __shared__ float wsum[8][9];
    if (lane == 0) {
#pragma unroll
        for (int e = 0; e < 8; e++) wsum[wid][e] = part[e];
    }
    __syncthreads();
    __shared__ float gsh[8];
    if (tid < 8) {
        float v = 0.0f;
#pragma unroll
        for (int w8 = 0; w8 < 8; w8++) v += wsum[w8][tid];
        gsh[tid] = v + bg[tid];
    }
    __syncthreads();
    if (tid == 0) {
        float m = -1e30f;
#pragma unroll
        for (int e = 0; e < 8; e++) m = fmaxf(m, gsh[e]);
        float ex[8], s = 0.0f;
#pragma unroll
        for (int e = 0; e < 8; e++) { ex[e] = __expf(gsh[e] - m); s += ex[e]; }
        const float inv = 1.0f / s;
#pragma unroll
        for (int e = 0; e < 8; e++) gsh[e] = ex[e] * inv;
    }
    __syncthreads();
    if (tid < 8) G[row * 8 + tid] = gsh[tid];
    float4 acc = xv;
#pragma unroll
    for (int e = 0; e < 8; e++) {
        const float ge = gsh[e];
        float4 b = ((const float4*)(b2 + e * HH))[tid];
        acc.x = fmaf(ge, b.x, acc.x); acc.y = fmaf(ge, b.y, acc.y);
        acc.z = fmaf(ge, b.z, acc.z); acc.w = fmaf(ge, b.w, acc.w);
    }
    ((float4*)(out + (long long)row * HH))[tid] = acc;
}

// ---------------- host side ----------------
extern "C" void kernel_launch(void* const* d_in, const int* in_sizes, int n_in,
                              void* d_out, int out_size)
{
    const float* x  = (const float*)d_in[0];
    const float* Wq = (const float*)d_in[1];
    const float* bq = (const float*)d_in[2];
    const float* Wk = (const float*)d_in[3];
    const float* bk = (const float*)d_in[4];
    const float* Wv = (const float*)d_in[5];
    const float* bv = (const float*)d_in[6];
    const float* Wo = (const float*)d_in[7];
    const float* bo = (const float*)d_in[8];
    const float* Wg = (const float*)d_in[9];
    const float* bg = (const float*)d_in[10];
    const float* W1 = (const float*)d_in[11];
    const float* b1 = (const float*)d_in[12];
    const float* W2 = (const float*)d_in[13];
    const float* b2 = (const float*)d_in[14];
    float* out = (float*)d_out;

    float *x2, *g;
    __half *x16, *qkv16, *s16, *ps, *vts, *a16, *x2s, *wqkvo, *w1ts, *w2ts, *hs;
    cudaGetSymbolAddress((void**)&x2, g_x2);
    cudaGetSymbolAddress((void**)&g, g_g);
    cudaGetSymbolAddress((void**)&x16, g_x16);
    cudaGetSymbolAddress((void**)&qkv16, g_qkv16);
    cudaGetSymbolAddress((void**)&s16, g_s16);
    cudaGetSymbolAddress((void**)&ps, g_ps);
    cudaGetSymbolAddress((void**)&vts, g_vts);
    cudaGetSymbolAddress((void**)&a16, g_a16);
    cudaGetSymbolAddress((void**)&x2s, g_x2s);
    cudaGetSymbolAddress((void**)&wqkvo, g_wqkvo);
    cudaGetSymbolAddress((void**)&w1ts, g_w1ts);
    cudaGetSymbolAddress((void**)&w2ts, g_w2ts);
    cudaGetSymbolAddress((void**)&hs, g_hs);

    cudaFuncSetAttribute(hmma_gemm<TE_BIAS_CVT16>, cudaFuncAttributeMaxDynamicSharedMemorySize, HG_SMEM);
    cudaFuncSetAttribute(hmma_gemm<TE_SCALE_CVT16>, cudaFuncAttributeMaxDynamicSharedMemorySize, HG_SMEM);
    cudaFuncSetAttribute(hmma_gemm<TE_CVT16>, cudaFuncAttributeMaxDynamicSharedMemorySize, HG_SMEM);
    cudaFuncSetAttribute(hmma_gemm<TE_BIAS_RESID_CVT1>, cudaFuncAttributeMaxDynamicSharedMemorySize, HG_SMEM);
    cudaFuncSetAttribute(hmma_gemm<TE_BIAS_RELU_CVT16>, cudaFuncAttributeMaxDynamicSharedMemorySize, HG_SMEM);
    cudaFuncSetAttribute(hmma_gemm<TE_GATED_RED>, cudaFuncAttributeMaxDynamicSharedMemorySize, HG_SMEM);

    PtrArr bnone = {};
    dim3 blk(256);

    // ONE side stream (first stream comes from the driver pool: delta=0 as
    // measured in R15; additional streams allocate device memory -> banned).
    // Created per call; never destroyed (destroying mid-capture invalidates).
    cudaStream_t s1;
    cudaStreamCreate(&s1);
    cudaEvent_t evRoot, evPrep, evO, evGates;
    cudaEventCreateWithFlags(&evRoot, cudaEventDisableTiming);
    cudaEventCreateWithFlags(&evPrep, cudaEventDisableTiming);
    cudaEventCreateWithFlags(&evO, cudaEventDisableTiming);
    cudaEventCreateWithFlags(&evGates, cudaEventDisableTiming);

    cudaEventRecord(evRoot, 0);
    cudaStreamWaitEvent(s1, evRoot, 0);

    // ---- side stream: MoE weight transposes (needed only at steps 6/7) ----
    {
        PtrArr wi;
        for (int e = 0; e < 8; e++) wi.p[e] = W1 + (long long)e * HH * DD;
        transpose_cvt<<<dim3(DD / 64, HH / 64, EE), blk, 0, s1>>>(wi, HH, DD, w1ts, (long long)HH * DD);
    }
    {
        PtrArr wi;
        for (int e = 0; e < 8; e++) wi.p[e] = W2 + (long long)e * DD * HH;
        transpose_cvt<<<dim3(HH / 64, DD / 64, EE), blk, 0, s1>>>(wi, DD, HH, w2ts, (long long)DD * HH);
    }
    cudaEventRecord(evPrep, s1);

    // ---- main stream: attention chain ----
    cvt16<<<(MT * HH / 4) / 256, blk>>>(x, x16);
    {
        PtrArr wi; wi.p[0] = Wq; wi.p[1] = Wk; wi.p[2] = Wv; wi.p[3] = Wo;
        transpose_cvt<<<dim3(HH / 64, HH / 64, 4), blk>>>(wi, HH, HH, wqkvo, (long long)HH * HH);
    }
    {
        PtrArr ba; ba.p[0] = bq; ba.p[1] = bk; ba.p[2] = bv;
        hmma_gemm<TE_BIAS_CVT16><<<dim3(HH / 128, MT / 128, 3), blk, HG_SMEM>>>(
            x16, 0, wqkvo, (long long)HH * HH, HH, nullptr, 0, ba,
            nullptr, qkv16, (long long)MT * HH, HH, nullptr, 0.0f);
    }
    const __half* q16 = qkv16;
    const __half* k16 = qkv16 + (long long)MT * HH;
    const __half* v16 = qkv16 + 2LL * MT * HH;

    hmma_gemm<TE_SCALE_CVT16><<<dim3(SQ / 128, SQ / 128, BB), blk, HG_SMEM>>>(
        q16, (long long)SQ * HH, k16, (long long)SQ * HH, HH,
        nullptr, 0, bnone, nullptr, s16, (long long)SQ * SQ, SQ, nullptr, 0.03125f);
    softmax_rows<<<BB * SQ, 256>>>(s16, ps);
    transpose_h<<<dim3(HH / 64, SQ / 64, BB), blk>>>(
        v16, (long long)SQ * HH, vts, (long long)HH * SQ, SQ, HH);
    hmma_gemm<TE_CVT16><<<dim3(HH / 128, SQ / 128, BB), blk, HG_SMEM>>>(
        ps, (long long)SQ * SQ, vts, (long long)HH * SQ, SQ,
        nullptr, 0, bnone, nullptr, a16, (long long)SQ * HH, HH, nullptr, 0.0f);

    {
        PtrArr ba; ba.p[0] = bo;
        hmma_gemm<TE_BIAS_RESID_CVT1><<<dim3(HH / 128, MT / 128, 1), blk, HG_SMEM>>>(
            a16, 0, wqkvo + 3ULL * HH * HH, 0, HH, x2, 0, ba, x, x2s, 0, HH,
            nullptr, 0.0f);
    }
    cudaEventRecord(evO, 0);

    // ---- side stream: gates + output base (overlaps up-proj) ----
    cudaStreamWaitEvent(s1, evO, 0);
    gates_out<<<MT, 256, 0, s1>>>(x2, Wg, bg, b2, g, out);
    cudaEventRecord(evGates, s1);

    // ---- main stream: MoE ----
    cudaStreamWaitEvent(0, evPrep, 0);
    {
        PtrArr ba;
        for (int e = 0; e < 8; e++) ba.p[e] = b1 + (long long)e * DD;
        hmma_gemm<TE_BIAS_RELU_CVT16><<<dim3(DD / 128, MT / 128, EE), blk, HG_SMEM>>>(
            x2s, 0, w1ts, (long long)HH * DD, HH, nullptr, 0, ba, nullptr,
            hs, (long long)MT * DD, DD, nullptr, 0.0f);
    }
    cudaStreamWaitEvent(0, evGates, 0);
    hmma_gemm<TE_GATED_RED><<<dim3(HH / 128, MT / 128, EE), blk, HG_SMEM>>>(
        hs, (long long)MT * DD, w2ts, (long long)DD * HH, DD, out, 0, bnone,
        nullptr, nullptr, 0, 0, g, 0.0f);
}